// round 9
// baseline (speedup 1.0000x reference)
#include <cuda_runtime.h>
#include <cuda_bf16.h>
#include <math.h>

#define BB 128
#define LL 512
#define DD 128
#define BL (BB*LL)
#define ML 512

// ---------------- scratch (static device globals; no allocations) ----------------
__device__ float g_seqs[BL*DD];
__device__ float g_Q   [BL*DD];
__device__ float g_q   [BL*DD];
__device__ float g_k   [BL*DD];
__device__ float g_v   [BL*DD];
__device__ float g_qp  [BL*DD];
__device__ float g_mha [BL*DD];
__device__ float g_tmp [BL*DD];
__device__ float g_attn[BB*LL*LL];            // fp32 raw scores
__device__ __nv_bfloat16 g_attnh[BB*LL*LL];   // bf16 normalized probs
__device__ float g_E   [BL*ML];
__device__ float g_cape[BL];

// ---------------- helpers ----------------
__device__ __forceinline__ float wredsum(float v){
    #pragma unroll
    for (int o=16;o>0;o>>=1) v += __shfl_xor_sync(0xffffffffu, v, o);
    return v;
}
__device__ __forceinline__ float wredmax(float v){
    #pragma unroll
    for (int o=16;o>0;o>>=1) v = fmaxf(v, __shfl_xor_sync(0xffffffffu, v, o));
    return v;
}
__device__ __forceinline__ void mma_tf32(float* d, const unsigned* a, const unsigned* b){
    asm volatile(
        "mma.sync.aligned.m16n8k8.row.col.f32.tf32.tf32.f32 "
        "{%0,%1,%2,%3},{%4,%5,%6,%7},{%8,%9},{%0,%1,%2,%3};"
        : "+f"(d[0]),"+f"(d[1]),"+f"(d[2]),"+f"(d[3])
        : "r"(a[0]),"r"(a[1]),"r"(a[2]),"r"(a[3]), "r"(b[0]),"r"(b[1]));
}
__device__ __forceinline__ void mma_bf16(float* d, const unsigned* a, const unsigned* b){
    asm volatile(
        "mma.sync.aligned.m16n8k16.row.col.f32.bf16.bf16.f32 "
        "{%0,%1,%2,%3},{%4,%5,%6,%7},{%8,%9},{%0,%1,%2,%3};"
        : "+f"(d[0]),"+f"(d[1]),"+f"(d[2]),"+f"(d[3])
        : "r"(a[0]),"r"(a[1]),"r"(a[2]),"r"(a[3]), "r"(b[0]),"r"(b[1]));
}
__device__ __forceinline__ void cpa16(void* s, const void* g){
    unsigned sa = (unsigned)__cvta_generic_to_shared(s);
    asm volatile("cp.async.cg.shared.global [%0],[%1],16;\n" :: "r"(sa),"l"(g));
}
__device__ __forceinline__ void cp_commit(){ asm volatile("cp.async.commit_group;\n"); }
template<int N> __device__ __forceinline__ void cp_wait(){ asm volatile("cp.async.wait_group %0;\n"::"n"(N)); }
__device__ __forceinline__ unsigned fu(float f){ return __float_as_uint(f); }

// ---------------- embedding gather ----------------
__global__ void embed_k(const float* __restrict__ item, const int* __restrict__ idx,
                        float* __restrict__ out){
    int row  = blockIdx.x*8 + (threadIdx.x>>5);
    int lane = threadIdx.x & 31;
    int id = idx[row];
    float4 v = *(const float4*)(item + (long long)id*DD + lane*4);
    const float s = 11.313708498984760f; // sqrt(128)
    v.x*=s; v.y*=s; v.z*=s; v.w*=s;
    *(float4*)(out + (long long)row*DD + lane*4) = v;
}

// ---------------- layernorm (optionally add per-row cape scalar first) ----------------
template<bool ADDC>
__global__ void ln_k(const float* __restrict__ x, const float* __restrict__ cape,
                     const float* __restrict__ gs, const float* __restrict__ gb,
                     float* __restrict__ y){
    int row  = blockIdx.x*8 + (threadIdx.x>>5);
    int lane = threadIdx.x & 31;
    const float* xr = x + (long long)row*DD;
    float4 v = *(const float4*)(xr + lane*4);
    if (ADDC){ float c = cape[row]; v.x+=c; v.y+=c; v.z+=c; v.w+=c; }
    float m = wredsum(v.x+v.y+v.z+v.w) * (1.0f/DD);
    float dx=v.x-m, dy=v.y-m, dz=v.z-m, dw=v.w-m;
    float var = wredsum(dx*dx+dy*dy+dz*dz+dw*dw) * (1.0f/DD);
    float r = rsqrtf(var + 1e-8f);
    float4 o;
    o.x = dx*r*gs[lane*4+0] + gb[lane*4+0];
    o.y = dy*r*gs[lane*4+1] + gb[lane*4+1];
    o.z = dz*r*gs[lane*4+2] + gb[lane*4+2];
    o.w = dw*r*gs[lane*4+3] + gb[lane*4+3];
    *(float4*)(y + (long long)row*DD + lane*4) = o;
}

// ---------------- fused causal softmax + CAPE ----------------
// Reads raw scores (fp32), writes normalized probs as bf16 (masked = exact 0),
// computes G=1-sigmoid(p), reversed cumsum P, interpolated gather of E, mean.
__global__ void softcape_k(const float* __restrict__ attn, __nv_bfloat16* __restrict__ ph,
                           const float* __restrict__ E, float* __restrict__ cape){
    __shared__ float es[8][ML];
    __shared__ float gsm[8][32][17];
    int w    = threadIdx.x>>5;
    int lane = threadIdx.x & 31;
    int row  = blockIdx.x*8 + w;
    int qi = row & (LL-1);
    const float* p = attn + (long long)row*LL;
    __nv_bfloat16* po = ph + (long long)row*LL;
    const float* er = E + (long long)row*ML;
    #pragma unroll
    for (int t=0;t<16;t++) es[w][t*32+lane] = er[t*32+lane];

    int nv = qi+1;
    float vals[16];
    float mx = -3.4e38f;
    #pragma unroll
    for (int t=0;t<16;t++){
        int j = t*32+lane;
        float s = (j<nv) ? p[j] : -3.4e38f;
        vals[t]=s; mx = fmaxf(mx, s);
    }
    mx = wredmax(mx);
    float sum = 0.f;
    #pragma unroll
    for (int t=0;t<16;t++){
        int j = t*32+lane;
        float e = (j<nv) ? __expf(vals[t]-mx) : 0.f;
        vals[t]=e; sum += e;
    }
    sum = wredsum(sum);
    float inv = 1.0f/sum;
    #pragma unroll
    for (int t=0;t<16;t++){
        int j = t*32+lane;
        float pv = vals[t]*inv;
        po[j] = __float2bfloat16(pv);
        float g = 1.0f/(1.0f+__expf(pv));   // 1 - sigmoid(pv); masked pv=0 -> 0.5 (matches ref)
        gsm[w][j>>4][j&15] = g;
    }
    __syncwarp();
    float cs = 0.f;
    #pragma unroll
    for (int t=0;t<16;t++) cs += gsm[w][lane][t];
    float sfx = cs;
    #pragma unroll
    for (int off=1;off<32;off<<=1){
        float o = __shfl_down_sync(0xffffffffu, sfx, off);
        if (lane+off < 32) sfx += o;
    }
    float tail = sfx - cs;
    float run = 0.f, acc = 0.f;
    #pragma unroll
    for (int t=15;t>=0;t--){
        run += gsm[w][lane][t];
        float P = run + tail;
        P = fminf(P, (float)(ML-1));
        float Pf = floorf(P);
        float fr = P - Pf;
        int pi = (int)Pf;
        int pc = (int)ceilf(P);
        float ef = es[w][pi];
        float ec = es[w][pc];
        acc += fr*ec + (1.0f-fr)*ef;
    }
    acc = wredsum(acc);
    if (lane==0) cape[row] = acc * (1.0f/LL);
}

// ---------------- final: LN + dot with pos/neg item embeddings ----------------
__global__ void final_k(const float* __restrict__ seqs, const float* __restrict__ item,
                        const float* __restrict__ gs, const float* __restrict__ gb,
                        const int* __restrict__ pos, const int* __restrict__ neg,
                        float* __restrict__ out){
    int row  = blockIdx.x*8 + (threadIdx.x>>5);
    int lane = threadIdx.x & 31;
    const float* xr = seqs + (long long)row*DD;
    float4 v = *(const float4*)(xr + lane*4);
    float m = wredsum(v.x+v.y+v.z+v.w) * (1.0f/DD);
    float dx=v.x-m, dy=v.y-m, dz=v.z-m, dw=v.w-m;
    float var = wredsum(dx*dx+dy*dy+dz*dz+dw*dw) * (1.0f/DD);
    float r = rsqrtf(var + 1e-8f);
    float f0 = dx*r*gs[lane*4+0] + gb[lane*4+0];
    float f1 = dy*r*gs[lane*4+1] + gb[lane*4+1];
    float f2 = dz*r*gs[lane*4+2] + gb[lane*4+2];
    float f3 = dw*r*gs[lane*4+3] + gb[lane*4+3];
    int pi = pos[row], ni = neg[row];
    float4 pe = *(const float4*)(item + (long long)pi*DD + lane*4);
    float4 ne = *(const float4*)(item + (long long)ni*DD + lane*4);
    float dp = f0*pe.x + f1*pe.y + f2*pe.z + f3*pe.w;
    float dn = f0*ne.x + f1*ne.y + f2*ne.z + f3*ne.w;
    dp = wredsum(dp); dn = wredsum(dn);
    if (lane==0){ out[row] = dp; out[BL+row] = dn; }
}

// ---------------- bf16 AV GEMM: mha = probs(bf16) @ v ----------------
// P: [B][512][512] bf16 row-major.  v: [B][512][128] fp32 (converted+transposed
// to bf16 in smem).  C: mha [B][512][128] fp32.  Causal: k-loop to m0+128.
// 256 thr, block tile 128x128, k32 steps, warp tile 64x32, mma m16n8k16 bf16.
__global__ __launch_bounds__(256)
void av_bf16(const __nv_bfloat16* __restrict__ P, const float* __restrict__ v,
             float* __restrict__ mha)
{
    const int b = blockIdx.y, m0 = blockIdx.x*128;
    const __nv_bfloat16* Pb = P + (long long)b*LL*LL;
    const float* vb = v + (long long)b*LL*DD;
    float* mb = mha + (long long)b*LL*DD;

    __shared__ __align__(16) __nv_bfloat16 AS[128*40];   // [m][k] halves, stride 40
    __shared__ __align__(16) __nv_bfloat16 VS[128*40];   // [n(d)][k] halves, stride 40

    const int tid=threadIdx.x, warp=tid>>5, lane=tid&31;
    const int wm=(warp&1)*64, wn=(warp>>1)*32;
    const int ar=lane>>2, ac=lane&3;
    const int kmax = m0+128;

    float acc[4][4][4];
    #pragma unroll
    for (int i=0;i<4;i++)
        #pragma unroll
        for (int j=0;j<4;j++)
            #pragma unroll
            for (int r=0;r<4;r++) acc[i][j][r]=0.f;

    for (int k0=0;k0<kmax;k0+=32){
        __syncthreads();
        // A tile: 128 rows x 32 halves (64B/row) via cp.async
        #pragma unroll
        for (int p8=0;p8<2;p8++){
            int t = p8*256+tid;
            int row = t>>2, c8=(t&3)*8;
            cpa16(&AS[row*40 + c8], Pb + (long long)(m0+row)*LL + k0 + c8);
        }
        cp_commit();
        // V tile: load fp32, convert bf16, transpose into VS[d][k]
        #pragma unroll
        for (int c=0;c<4;c++){
            int idx=c*256+tid;
            int kk = idx&31, d4=(idx>>5)*4;
            float4 vv = *(const float4*)(vb + (long long)(k0+kk)*DD + d4);
            VS[(d4+0)*40+kk]=__float2bfloat16(vv.x);
            VS[(d4+1)*40+kk]=__float2bfloat16(vv.y);
            VS[(d4+2)*40+kk]=__float2bfloat16(vv.z);
            VS[(d4+3)*40+kk]=__float2bfloat16(vv.w);
        }
        cp_wait<0>();
        __syncthreads();
        #pragma unroll
        for (int ks=0;ks<2;ks++){
            const int kc=ks*16;
            unsigned af[4][4];
            #pragma unroll
            for (int mi=0;mi<4;mi++){
                int r0=wm+mi*16+ar;
                af[mi][0]=*(const unsigned*)&AS[(r0  )*40 + kc + ac*2    ];
                af[mi][1]=*(const unsigned*)&AS[(r0+8)*40 + kc + ac*2    ];
                af[mi][2]=*(const unsigned*)&AS[(r0  )*40 + kc + ac*2 + 8];
                af[mi][3]=*(const unsigned*)&AS[(r0+8)*40 + kc + ac*2 + 8];
            }
            #pragma unroll
            for (int ni=0;ni<4;ni++){
                int n=wn+ni*8+ar;
                unsigned bf[2];
                bf[0]=*(const unsigned*)&VS[n*40 + kc + ac*2    ];
                bf[1]=*(const unsigned*)&VS[n*40 + kc + ac*2 + 8];
                #pragma unroll
                for (int mi=0;mi<4;mi++) mma_bf16(acc[mi][ni], af[mi], bf);
            }
        }
    }

    const int er=lane>>2, ec=(lane&3)*2;
    #pragma unroll
    for (int mi=0;mi<4;mi++){
        #pragma unroll
        for (int half=0; half<2; half++){
            long long gm = m0 + wm + mi*16 + er + half*8;
            float* crow = mb + gm*(long long)DD;
            #pragma unroll
            for (int ni=0;ni<4;ni++){
                int gn = wn + ni*8 + ec;
                float2 o; o.x=acc[mi][ni][half*2+0]; o.y=acc[mi][ni][half*2+1];
                *(float2*)(crow + gn) = o;
            }
        }
    }
}

// ---------------- pipelined TF32 GEMM ----------------
// C = act(alpha*A.op(B)+bias)+res.  A [M,K] row-major (z-strided by sA).
// TRANSB: B [N,K] (C=A.B^T); else B [K,N].  cp.async 2-stage, 128x128x16 tiles,
// 256 thr, warp tile 64x32.
// DUAL: grid.x==2 selects (Bm,bias,C,ACT) / (Bm2,bias2,C2,ACT2); n0=0.
// SKIPUP: skip tiles fully above causal diagonal (scores).
template<bool TRANSB, int ACT, int ACT2, bool DUAL, bool SKIPUP>
__global__ __launch_bounds__(256,2)
void gemm_p(const float* __restrict__ A, const float* __restrict__ Bm,
            const float* __restrict__ bias, const float* __restrict__ res,
            float* __restrict__ C,
            const float* __restrict__ Bm2, const float* __restrict__ bias2,
            float* __restrict__ C2,
            int M, int N, int K,
            long long sA, long long sB, long long sC, float alpha)
{
    if (SKIPUP && (int)blockIdx.x > (int)blockIdx.y) return;
    const int bz = blockIdx.z;
    A += (long long)bz*sA;
    int actv = ACT;
    if (DUAL){
        if (blockIdx.x == 1){ Bm = Bm2; bias = bias2; C = C2; actv = ACT2; }
    } else {
        Bm += (long long)bz*sB;
        C  += (long long)bz*sC;
        if (res) res += (long long)bz*sC;
    }

    __shared__ __align__(16) float As[2][128*20];
    __shared__ __align__(16) float Bs[2][2560];
    const int tid=threadIdx.x, warp=tid>>5, lane=tid&31;
    const int wm=(warp&1)*64, wn=(warp>>1)*32;
    const int m0=blockIdx.y*128;
    const int n0=DUAL ? 0 : blockIdx.x*128;
    const int ar=lane>>2, ac=lane&3;
    const int nk = K>>4;

    float acc[4][4][4];
    #pragma unroll
    for (int i=0;i<4;i++)
        #pragma unroll
        for (int j=0;j<4;j++)
            #pragma unroll
            for (int r=0;r<4;r++) acc[i][j][r]=0.f;

    {
        #pragma unroll
        for (int p=0;p<2;p++){
            int t=p*256+tid, row=t>>2, c4=(t&3)*4;
            cpa16(&As[0][row*20+c4], A + (long long)(m0+row)*K + c4);
        }
        if (TRANSB){
            #pragma unroll
            for (int p=0;p<2;p++){
                int t=p*256+tid, row=t>>2, c4=(t&3)*4;
                cpa16(&Bs[0][row*20+c4], Bm + (long long)(n0+row)*K + c4);
            }
        } else {
            #pragma unroll
            for (int p=0;p<2;p++){
                int t=p*256+tid, kk=t>>5, c4=(t&31)*4;
                cpa16(&Bs[0][kk*136+c4], Bm + (long long)kk*N + n0 + c4);
            }
        }
        cp_commit();
    }

    for (int i=0;i<nk;i++){
        if (i+1<nk){
            int bn=(i+1)&1, k0=(i+1)<<4;
            #pragma unroll
            for (int p=0;p<2;p++){
                int t=p*256+tid, row=t>>2, c4=(t&3)*4;
                cpa16(&As[bn][row*20+c4], A + (long long)(m0+row)*K + k0 + c4);
            }
            if (TRANSB){
                #pragma unroll
                for (int p=0;p<2;p++){
                    int t=p*256+tid, row=t>>2, c4=(t&3)*4;
                    cpa16(&Bs[bn][row*20+c4], Bm + (long long)(n0+row)*K + k0 + c4);
                }
            } else {
                #pragma unroll
                for (int p=0;p<2;p++){
                    int t=p*256+tid, kk=t>>5, c4=(t&31)*4;
                    cpa16(&Bs[bn][kk*136+c4], Bm + (long long)(k0+kk)*N + n0 + c4);
                }
            }
            cp_commit();
            cp_wait<1>();
        } else {
            cp_wait<0>();
        }
        __syncthreads();
        const int bc=i&1;
        #pragma unroll
        for (int s8=0;s8<2;s8++){
            const int kb=s8*8;
            unsigned af[4][4];
            #pragma unroll
            for (int mi=0;mi<4;mi++){
                int r0=wm+mi*16+ar;
                af[mi][0]=fu(As[bc][(r0  )*20+kb+ac  ]);
                af[mi][1]=fu(As[bc][(r0+8)*20+kb+ac  ]);
                af[mi][2]=fu(As[bc][(r0  )*20+kb+ac+4]);
                af[mi][3]=fu(As[bc][(r0+8)*20+kb+ac+4]);
            }
            #pragma unroll
            for (int ni=0;ni<4;ni++){
                unsigned bf[2];
                if (TRANSB){
                    int nr=wn+ni*8+ar;
                    bf[0]=fu(Bs[bc][nr*20+kb+ac  ]);
                    bf[1]=fu(Bs[bc][nr*20+kb+ac+4]);
                } else {
                    int nc=wn+ni*8+ar;
                    bf[0]=fu(Bs[bc][(kb+ac  )*136+nc]);
                    bf[1]=fu(Bs[bc][(kb+ac+4)*136+nc]);
                }
                #pragma unroll
                for (int mi=0;mi<4;mi++) mma_tf32(acc[mi][ni], af[mi], bf);
            }
        }
        __syncthreads();
    }

    const int er=lane>>2, ec=(lane&3)*2;
    #pragma unroll
    for (int mi=0;mi<4;mi++){
        #pragma unroll
        for (int half=0; half<2; half++){
            long long gm = m0 + wm + mi*16 + er + half*8;
            float* crow = C + gm*(long long)N;
            const float* rrow = res ? (res + gm*(long long)N) : nullptr;
            #pragma unroll
            for (int ni=0;ni<4;ni++){
                int gn = n0 + wn + ni*8 + ec;
                float v0 = acc[mi][ni][half*2+0]*alpha;
                float v1 = acc[mi][ni][half*2+1]*alpha;
                if (bias){ v0 += bias[gn]; v1 += bias[gn+1]; }
                if (actv==1){ v0 = fmaxf(v0,0.f); v1 = fmaxf(v1,0.f); }
                if (actv==2){ v0 = v0/(1.0f+__expf(-v0)); v1 = v1/(1.0f+__expf(-v1)); }
                if (rrow){ v0 += rrow[gn]; v1 += rrow[gn+1]; }
                float2 o; o.x=v0; o.y=v1;
                *(float2*)(crow + gn) = o;
            }
        }
    }
}

// ---------------- host orchestration ----------------
extern "C" void kernel_launch(void* const* d_in, const int* in_sizes, int n_in,
                              void* d_out, int out_size){
    (void)in_sizes; (void)n_in; (void)out_size;
    const float* item   = (const float*)d_in[0];
    const float* posemb = (const float*)d_in[1];
    const float* pre_w  = (const float*)d_in[2];
    const float* pre_b  = (const float*)d_in[3];
    const float* ln1_s  = (const float*)d_in[4];
    const float* ln1_b  = (const float*)d_in[5];
    const float* in_w   = (const float*)d_in[6];
    const float* in_b   = (const float*)d_in[7];
    const float* out_w  = (const float*)d_in[8];
    const float* out_b  = (const float*)d_in[9];
    const float* ln2_s  = (const float*)d_in[10];
    const float* ln2_b  = (const float*)d_in[11];
    const float* c1_w   = (const float*)d_in[12];
    const float* c1_b   = (const float*)d_in[13];
    const float* c2_w   = (const float*)d_in[14];
    const float* c2_b   = (const float*)d_in[15];
    const float* lnf_s  = (const float*)d_in[16];
    const float* lnf_b  = (const float*)d_in[17];
    const int* logs = (const int*)d_in[19];
    const int* poss = (const int*)d_in[20];
    const int* negs = (const int*)d_in[21];
    float* out = (float*)d_out;

    float *seqs,*Q,*q,*k,*v,*qp,*mha,*tmp,*attn,*E,*cape;
    __nv_bfloat16* attnh;
    cudaGetSymbolAddress((void**)&seqs, g_seqs);
    cudaGetSymbolAddress((void**)&Q,    g_Q);
    cudaGetSymbolAddress((void**)&q,    g_q);
    cudaGetSymbolAddress((void**)&k,    g_k);
    cudaGetSymbolAddress((void**)&v,    g_v);
    cudaGetSymbolAddress((void**)&qp,   g_qp);
    cudaGetSymbolAddress((void**)&mha,  g_mha);
    cudaGetSymbolAddress((void**)&tmp,  g_tmp);
    cudaGetSymbolAddress((void**)&attn, g_attn);
    cudaGetSymbolAddress((void**)&attnh,g_attnh);
    cudaGetSymbolAddress((void**)&E,    g_E);
    cudaGetSymbolAddress((void**)&cape, g_cape);

    const int ROWB = BL/8;
    const float scale = 0.08838834764831845f; // 1/sqrt(128)

    embed_k<<<ROWB,256>>>(item, logs, seqs);

    for (int i=0;i<2;i++){
        const float* wq = in_w + (long long)i*3*DD*DD;
        const float* wk = wq + DD*DD;
        const float* wv = wk + DD*DD;
        const float* bq = in_b + (long long)i*3*DD;
        const float* bk = bq + DD;
        const float* bv = bk + DD;

        ln_k<false><<<ROWB,256>>>(seqs, nullptr, ln1_s+i*DD, ln1_b+i*DD, Q);

        // dual GEMMs: (q, qp) from Q;  (k, v) from seqs
        dim3 gd(2, BL/128);
        gemm_p<true,0,2,true,false><<<gd,256>>>(Q, wq, bq, nullptr, q,
                                                pre_w, pre_b, qp,
                                                BL, DD, DD, 0,0,0, 1.f);
        gemm_p<true,0,0,true,false><<<gd,256>>>(seqs, wk, bk, nullptr, k,
                                                wv, bv, v,
                                                BL, DD, DD, 0,0,0, 1.f);

        // E = qp @ pos_emb   [BL, 512]
        dim3 ge(4, BL/128);
        gemm_p<false,0,0,false,false><<<ge,256>>>(qp, posemb, nullptr, nullptr, E,
                                                  nullptr,nullptr,nullptr,
                                                  BL, ML, DD, 0,0,0, 1.f);

        // scores = q.k^T * scale  (skip fully-masked upper tiles)
        dim3 gsc(4,4,BB);
        gemm_p<true,0,0,false,true><<<gsc,256>>>(q, k, nullptr, nullptr, attn,
            nullptr,nullptr,nullptr,
            LL, LL, DD, (long long)LL*DD, (long long)LL*DD, (long long)LL*LL, scale);

        // fused softmax + CAPE (reads fp32 scores, writes bf16 probs + cape)
        softcape_k<<<ROWB,256>>>(attn, attnh, E, cape);

        // mha = probs(bf16) @ v   (causal K-limit per m-tile)
        av_bf16<<<dim3(4,BB),256>>>(attnh, v, mha);

        // seqs = Q + mha.out_w^T + out_b
        dim3 gl(1, BL/128);
        gemm_p<true,0,0,false,false><<<gl,256>>>(mha, out_w+(long long)i*DD*DD,
                                                 out_b+i*DD, Q, seqs,
                                                 nullptr,nullptr,nullptr,
                                                 BL, DD, DD, 0,0,0, 1.f);

        // seqs = LN2(seqs + cape)  -> X (stored in Q buffer)
        ln_k<true><<<ROWB,256>>>(seqs, cape, ln2_s+i*DD, ln2_b+i*DD, Q);

        // FFN
        gemm_p<true,1,0,false,false><<<gl,256>>>(Q, c1_w+(long long)i*DD*DD,
                                                 c1_b+i*DD, nullptr, tmp,
                                                 nullptr,nullptr,nullptr,
                                                 BL, DD, DD, 0,0,0, 1.f);
        gemm_p<true,0,0,false,false><<<gl,256>>>(tmp, c2_w+(long long)i*DD*DD,
                                                 c2_b+i*DD, Q, seqs,
                                                 nullptr,nullptr,nullptr,
                                                 BL, DD, DD, 0,0,0, 1.f);
    }

    final_k<<<ROWB,256>>>(seqs, item, lnf_s, lnf_b, poss, negs, out);
}

// round 10
// speedup vs baseline: 1.1487x; 1.1487x over previous
#include <cuda_runtime.h>
#include <cuda_bf16.h>
#include <math.h>

#define BB 128
#define LL 512
#define DD 128
#define BL (BB*LL)
#define ML 512

// ---------------- scratch (static device globals; no allocations) ----------------
__device__ float g_seqs[BL*DD];
__device__ float g_Q   [BL*DD];
__device__ float g_q   [BL*DD];
__device__ float g_k   [BL*DD];
__device__ float g_v   [BL*DD];
__device__ float g_qp  [BL*DD];
__device__ float g_mha [BL*DD];
__device__ float g_tmp [BL*DD];
__device__ float g_attn[BB*LL*LL];            // fp32 raw scores
__device__ __nv_bfloat16 g_attnh[BB*LL*LL];   // bf16 normalized probs
__device__ float g_E   [BL*ML];
__device__ float g_cape[BL];

// ---------------- helpers ----------------
__device__ __forceinline__ float wredsum(float v){
    #pragma unroll
    for (int o=16;o>0;o>>=1) v += __shfl_xor_sync(0xffffffffu, v, o);
    return v;
}
__device__ __forceinline__ float wredmax(float v){
    #pragma unroll
    for (int o=16;o>0;o>>=1) v = fmaxf(v, __shfl_xor_sync(0xffffffffu, v, o));
    return v;
}
__device__ __forceinline__ void mma_tf32(float* d, const unsigned* a, const unsigned* b){
    asm volatile(
        "mma.sync.aligned.m16n8k8.row.col.f32.tf32.tf32.f32 "
        "{%0,%1,%2,%3},{%4,%5,%6,%7},{%8,%9},{%0,%1,%2,%3};"
        : "+f"(d[0]),"+f"(d[1]),"+f"(d[2]),"+f"(d[3])
        : "r"(a[0]),"r"(a[1]),"r"(a[2]),"r"(a[3]), "r"(b[0]),"r"(b[1]));
}
__device__ __forceinline__ void mma_bf16(float* d, const unsigned* a, const unsigned* b){
    asm volatile(
        "mma.sync.aligned.m16n8k16.row.col.f32.bf16.bf16.f32 "
        "{%0,%1,%2,%3},{%4,%5,%6,%7},{%8,%9},{%0,%1,%2,%3};"
        : "+f"(d[0]),"+f"(d[1]),"+f"(d[2]),"+f"(d[3])
        : "r"(a[0]),"r"(a[1]),"r"(a[2]),"r"(a[3]), "r"(b[0]),"r"(b[1]));
}
__device__ __forceinline__ void cpa16(void* s, const void* g){
    unsigned sa = (unsigned)__cvta_generic_to_shared(s);
    asm volatile("cp.async.cg.shared.global [%0],[%1],16;\n" :: "r"(sa),"l"(g));
}
__device__ __forceinline__ void cp_commit(){ asm volatile("cp.async.commit_group;\n"); }
template<int N> __device__ __forceinline__ void cp_wait(){ asm volatile("cp.async.wait_group %0;\n"::"n"(N)); }
__device__ __forceinline__ unsigned fu(float f){ return __float_as_uint(f); }
__device__ __forceinline__ unsigned pbf2(float a, float b){
    __nv_bfloat162 h = __floats2bfloat162_rn(a,b);
    return *(unsigned*)&h;
}

// ---------------- embedding gather ----------------
__global__ void embed_k(const float* __restrict__ item, const int* __restrict__ idx,
                        float* __restrict__ out){
    int row  = blockIdx.x*8 + (threadIdx.x>>5);
    int lane = threadIdx.x & 31;
    int id = idx[row];
    float4 v = *(const float4*)(item + (long long)id*DD + lane*4);
    const float s = 11.313708498984760f; // sqrt(128)
    v.x*=s; v.y*=s; v.z*=s; v.w*=s;
    *(float4*)(out + (long long)row*DD + lane*4) = v;
}

// ---------------- layernorm (optionally add per-row cape scalar first) ----------------
template<bool ADDC>
__global__ void ln_k(const float* __restrict__ x, const float* __restrict__ cape,
                     const float* __restrict__ gs, const float* __restrict__ gb,
                     float* __restrict__ y){
    int row  = blockIdx.x*8 + (threadIdx.x>>5);
    int lane = threadIdx.x & 31;
    const float* xr = x + (long long)row*DD;
    float4 v = *(const float4*)(xr + lane*4);
    if (ADDC){ float c = cape[row]; v.x+=c; v.y+=c; v.z+=c; v.w+=c; }
    float m = wredsum(v.x+v.y+v.z+v.w) * (1.0f/DD);
    float dx=v.x-m, dy=v.y-m, dz=v.z-m, dw=v.w-m;
    float var = wredsum(dx*dx+dy*dy+dz*dz+dw*dw) * (1.0f/DD);
    float r = rsqrtf(var + 1e-8f);
    float4 o;
    o.x = dx*r*gs[lane*4+0] + gb[lane*4+0];
    o.y = dy*r*gs[lane*4+1] + gb[lane*4+1];
    o.z = dz*r*gs[lane*4+2] + gb[lane*4+2];
    o.w = dw*r*gs[lane*4+3] + gb[lane*4+3];
    *(float4*)(y + (long long)row*DD + lane*4) = o;
}

// ---------------- fused causal softmax + CAPE ----------------
__global__ void softcape_k(const float* __restrict__ attn, __nv_bfloat16* __restrict__ ph,
                           const float* __restrict__ E, float* __restrict__ cape){
    __shared__ float es[8][ML];
    __shared__ float gsm[8][32][17];
    int w    = threadIdx.x>>5;
    int lane = threadIdx.x & 31;
    int row  = blockIdx.x*8 + w;
    int qi = row & (LL-1);
    const float* p = attn + (long long)row*LL;
    __nv_bfloat16* po = ph + (long long)row*LL;
    const float* er = E + (long long)row*ML;
    #pragma unroll
    for (int t=0;t<16;t++) es[w][t*32+lane] = er[t*32+lane];

    int nv = qi+1;
    float vals[16];
    float mx = -3.4e38f;
    #pragma unroll
    for (int t=0;t<16;t++){
        int j = t*32+lane;
        float s = (j<nv) ? p[j] : -3.4e38f;
        vals[t]=s; mx = fmaxf(mx, s);
    }
    mx = wredmax(mx);
    float sum = 0.f;
    #pragma unroll
    for (int t=0;t<16;t++){
        int j = t*32+lane;
        float e = (j<nv) ? __expf(vals[t]-mx) : 0.f;
        vals[t]=e; sum += e;
    }
    sum = wredsum(sum);
    float inv = 1.0f/sum;
    #pragma unroll
    for (int t=0;t<16;t++){
        int j = t*32+lane;
        float pv = vals[t]*inv;
        po[j] = __float2bfloat16(pv);
        float g = 1.0f/(1.0f+__expf(pv));   // 1 - sigmoid(pv); masked pv=0 -> 0.5 (matches ref)
        gsm[w][j>>4][j&15] = g;
    }
    __syncwarp();
    float cs = 0.f;
    #pragma unroll
    for (int t=0;t<16;t++) cs += gsm[w][lane][t];
    float sfx = cs;
    #pragma unroll
    for (int off=1;off<32;off<<=1){
        float o = __shfl_down_sync(0xffffffffu, sfx, off);
        if (lane+off < 32) sfx += o;
    }
    float tail = sfx - cs;
    float run = 0.f, acc = 0.f;
    #pragma unroll
    for (int t=15;t>=0;t--){
        run += gsm[w][lane][t];
        float P = run + tail;
        P = fminf(P, (float)(ML-1));
        float Pf = floorf(P);
        float fr = P - Pf;
        int pi = (int)Pf;
        int pc = (int)ceilf(P);
        float ef = es[w][pi];
        float ec = es[w][pc];
        acc += fr*ec + (1.0f-fr)*ef;
    }
    acc = wredsum(acc);
    if (lane==0) cape[row] = acc * (1.0f/LL);
}

// ---------------- final: LN + dot with pos/neg item embeddings ----------------
__global__ void final_k(const float* __restrict__ seqs, const float* __restrict__ item,
                        const float* __restrict__ gs, const float* __restrict__ gb,
                        const int* __restrict__ pos, const int* __restrict__ neg,
                        float* __restrict__ out){
    int row  = blockIdx.x*8 + (threadIdx.x>>5);
    int lane = threadIdx.x & 31;
    const float* xr = seqs + (long long)row*DD;
    float4 v = *(const float4*)(xr + lane*4);
    float m = wredsum(v.x+v.y+v.z+v.w) * (1.0f/DD);
    float dx=v.x-m, dy=v.y-m, dz=v.z-m, dw=v.w-m;
    float var = wredsum(dx*dx+dy*dy+dz*dz+dw*dw) * (1.0f/DD);
    float r = rsqrtf(var + 1e-8f);
    float f0 = dx*r*gs[lane*4+0] + gb[lane*4+0];
    float f1 = dy*r*gs[lane*4+1] + gb[lane*4+1];
    float f2 = dz*r*gs[lane*4+2] + gb[lane*4+2];
    float f3 = dw*r*gs[lane*4+3] + gb[lane*4+3];
    int pi = pos[row], ni = neg[row];
    float4 pe = *(const float4*)(item + (long long)pi*DD + lane*4);
    float4 ne = *(const float4*)(item + (long long)ni*DD + lane*4);
    float dp = f0*pe.x + f1*pe.y + f2*pe.z + f3*pe.w;
    float dn = f0*ne.x + f1*ne.y + f2*ne.z + f3*ne.w;
    dp = wredsum(dp); dn = wredsum(dn);
    if (lane==0){ out[row] = dp; out[BL+row] = dn; }
}

// ---------------- pipelined TF32 GEMM, k32 steps, dynamic smem ----------------
// C = act(alpha*A.B^T + bias) + res.  A [M,K], B [N,K] row-major.  K%32==0.
// 128x128 block tile, 256 thr, warp tile 64x32, 2-stage cp.async.
// DUAL: grid.x==2 selects (Bm,bias,C,ACT) / (Bm2,bias2,C2,ACT2); n0=0.
// SKIPUP: skip tiles fully above causal diagonal (scores).
template<int ACT, int ACT2, bool DUAL, bool SKIPUP>
__global__ __launch_bounds__(256,2)
void gemm_p(const float* __restrict__ A, const float* __restrict__ Bm,
            const float* __restrict__ bias, const float* __restrict__ res,
            float* __restrict__ C,
            const float* __restrict__ Bm2, const float* __restrict__ bias2,
            float* __restrict__ C2,
            int M, int N, int K,
            long long sA, long long sB, long long sC, float alpha)
{
    if (SKIPUP && (int)blockIdx.x > (int)blockIdx.y) return;
    const int bz = blockIdx.z;
    A += (long long)bz*sA;
    int actv = ACT;
    if (DUAL){
        if (blockIdx.x == 1){ Bm = Bm2; bias = bias2; C = C2; actv = ACT2; }
    } else {
        Bm += (long long)bz*sB;
        C  += (long long)bz*sC;
        if (res) res += (long long)bz*sC;
    }

    extern __shared__ float sm_g[];
    float* As = sm_g;            // 2 x [128][36]
    float* Bs = sm_g + 2*4608;   // 2 x [128][36]

    const int tid=threadIdx.x, warp=tid>>5, lane=tid&31;
    const int wm=(warp&1)*64, wn=(warp>>1)*32;
    const int m0=blockIdx.y*128;
    const int n0=DUAL ? 0 : blockIdx.x*128;
    const int ar=lane>>2, ac=lane&3;
    const int nk = K>>5;
    const int lrow = tid>>3, lc4 = (tid&7)*4;

    float acc[4][4][4];
    #pragma unroll
    for (int i=0;i<4;i++)
        #pragma unroll
        for (int j=0;j<4;j++)
            #pragma unroll
            for (int r=0;r<4;r++) acc[i][j][r]=0.f;

    // stage 0
    {
        float* as = As; float* bs = Bs;
        #pragma unroll
        for (int p=0;p<4;p++){
            int row = p*32 + lrow;
            cpa16(&as[row*36+lc4], A  + (long long)(m0+row)*K + lc4);
            cpa16(&bs[row*36+lc4], Bm + (long long)(n0+row)*K + lc4);
        }
        cp_commit();
    }

    for (int i=0;i<nk;i++){
        if (i+1<nk){
            int bn=(i+1)&1, k0=(i+1)<<5;
            float* as = As + bn*4608; float* bs = Bs + bn*4608;
            #pragma unroll
            for (int p=0;p<4;p++){
                int row = p*32 + lrow;
                cpa16(&as[row*36+lc4], A  + (long long)(m0+row)*K + k0 + lc4);
                cpa16(&bs[row*36+lc4], Bm + (long long)(n0+row)*K + k0 + lc4);
            }
            cp_commit();
            cp_wait<1>();
        } else {
            cp_wait<0>();
        }
        __syncthreads();
        const float* as = As + (i&1)*4608;
        const float* bs = Bs + (i&1)*4608;
        #pragma unroll
        for (int s8=0;s8<4;s8++){
            const int kb=s8*8;
            unsigned af[4][4];
            #pragma unroll
            for (int mi=0;mi<4;mi++){
                int r0=wm+mi*16+ar;
                af[mi][0]=fu(as[(r0  )*36+kb+ac  ]);
                af[mi][1]=fu(as[(r0+8)*36+kb+ac  ]);
                af[mi][2]=fu(as[(r0  )*36+kb+ac+4]);
                af[mi][3]=fu(as[(r0+8)*36+kb+ac+4]);
            }
            #pragma unroll
            for (int ni=0;ni<4;ni++){
                int nr=wn+ni*8+ar;
                unsigned bf[2];
                bf[0]=fu(bs[nr*36+kb+ac  ]);
                bf[1]=fu(bs[nr*36+kb+ac+4]);
                #pragma unroll
                for (int mi=0;mi<4;mi++) mma_tf32(acc[mi][ni], af[mi], bf);
            }
        }
        __syncthreads();
    }

    const int er=lane>>2, ec=(lane&3)*2;
    #pragma unroll
    for (int mi=0;mi<4;mi++){
        #pragma unroll
        for (int half=0; half<2; half++){
            long long gm = m0 + wm + mi*16 + er + half*8;
            float* crow = C + gm*(long long)N;
            const float* rrow = res ? (res + gm*(long long)N) : nullptr;
            #pragma unroll
            for (int ni=0;ni<4;ni++){
                int gn = n0 + wn + ni*8 + ec;
                float v0 = acc[mi][ni][half*2+0]*alpha;
                float v1 = acc[mi][ni][half*2+1]*alpha;
                if (bias){ v0 += bias[gn]; v1 += bias[gn+1]; }
                if (actv==1){ v0 = fmaxf(v0,0.f); v1 = fmaxf(v1,0.f); }
                if (actv==2){ v0 = v0/(1.0f+__expf(-v0)); v1 = v1/(1.0f+__expf(-v1)); }
                if (rrow){ v0 += rrow[gn]; v1 += rrow[gn+1]; }
                float2 o; o.x=v0; o.y=v1;
                *(float2*)(crow + gn) = o;
            }
        }
    }
}

// ---------------- bf16 single-shot GEMM for E = qp @ pos_emb ----------------
// A = qp [BL,128] fp32 -> bf16. B = pos_emb [128,512] fp32 -> bf16 transposed.
// K=128 loaded entirely; no k-loop. Block tile 128x128, warp tile 64x32, k16 mma.
__global__ __launch_bounds__(256,2)
void gemm_e(const float* __restrict__ qp, const float* __restrict__ pe,
            float* __restrict__ E)
{
    extern __shared__ __nv_bfloat16 sm_e[];
    __nv_bfloat16* AS = sm_e;            // [128 m][136 k]
    __nv_bfloat16* BS = sm_e + 128*136;  // [128 n][136 k]

    const int tid=threadIdx.x, warp=tid>>5, lane=tid&31;
    const int n0=blockIdx.x*128;
    const long long m0=(long long)blockIdx.y*128;
    const int wm=(warp&1)*64, wn=(warp>>1)*32;
    const int ar=lane>>2, ac=lane&3;

    // A: qp rows -> AS[m][k] (coalesced fp32 loads, packed bf16 stores)
    #pragma unroll
    for (int p=0;p<16;p++){
        int f=p*256+tid;
        int m=f>>5, k4=(f&31)*4;
        float4 a = *(const float4*)(qp + (m0+m)*DD + k4);
        uint2 u; u.x=pbf2(a.x,a.y); u.y=pbf2(a.z,a.w);
        *(uint2*)&AS[m*136+k4] = u;
    }
    // B: pe[k][n] -> BS[n][k] (coalesced over n, k-packed stores)
    #pragma unroll
    for (int p=0;p<16;p++){
        int f=p*256+tid;
        int n=f&127, kb=(f>>7)*4;
        float b0=pe[(kb+0)*ML+n0+n], b1=pe[(kb+1)*ML+n0+n];
        float b2=pe[(kb+2)*ML+n0+n], b3=pe[(kb+3)*ML+n0+n];
        uint2 u; u.x=pbf2(b0,b1); u.y=pbf2(b2,b3);
        *(uint2*)&BS[n*136+kb] = u;
    }
    __syncthreads();

    float acc[4][4][4];
    #pragma unroll
    for (int i=0;i<4;i++)
        #pragma unroll
        for (int j=0;j<4;j++)
            #pragma unroll
            for (int r=0;r<4;r++) acc[i][j][r]=0.f;

    #pragma unroll
    for (int ks=0;ks<8;ks++){
        const int kc=ks*16;
        unsigned af[4][4];
        #pragma unroll
        for (int mi=0;mi<4;mi++){
            int r0=wm+mi*16+ar;
            af[mi][0]=*(const unsigned*)&AS[(r0  )*136+kc+ac*2  ];
            af[mi][1]=*(const unsigned*)&AS[(r0+8)*136+kc+ac*2  ];
            af[mi][2]=*(const unsigned*)&AS[(r0  )*136+kc+8+ac*2];
            af[mi][3]=*(const unsigned*)&AS[(r0+8)*136+kc+8+ac*2];
        }
        #pragma unroll
        for (int ni=0;ni<4;ni++){
            int n=wn+ni*8+ar;
            unsigned bf[2];
            bf[0]=*(const unsigned*)&BS[n*136+kc+ac*2  ];
            bf[1]=*(const unsigned*)&BS[n*136+kc+8+ac*2];
            #pragma unroll
            for (int mi=0;mi<4;mi++) mma_bf16(acc[mi][ni], af[mi], bf);
        }
    }

    const int er=lane>>2, ec=(lane&3)*2;
    #pragma unroll
    for (int mi=0;mi<4;mi++){
        #pragma unroll
        for (int half=0; half<2; half++){
            long long gm = m0 + wm + mi*16 + er + half*8;
            float* crow = E + gm*(long long)ML;
            #pragma unroll
            for (int ni=0;ni<4;ni++){
                int gn = n0 + wn + ni*8 + ec;
                float2 o; o.x=acc[mi][ni][half*2+0]; o.y=acc[mi][ni][half*2+1];
                *(float2*)(crow + gn) = o;
            }
        }
    }
}

// ---------------- bf16 AV GEMM: mha = probs(bf16) @ v, double-buffered ----------------
// P [B][512][512] bf16, v [B][512][128] fp32 (cvt+transposed to bf16 smem).
// Block tile 128x128, k32 steps, warp tile 64x32, causal k-limit m0+128.
__global__ __launch_bounds__(256,2)
void av_bf16(const __nv_bfloat16* __restrict__ P, const float* __restrict__ v,
             float* __restrict__ mha)
{
    const int b=blockIdx.y, m0=blockIdx.x*128;
    const __nv_bfloat16* Pb = P + (long long)b*LL*LL;
    const float* vb = v + (long long)b*LL*DD;
    float* mb = mha + (long long)b*LL*DD;

    __shared__ __align__(16) __nv_bfloat16 AS[2][128*40];
    __shared__ __align__(16) __nv_bfloat16 VS[2][128*40];

    const int tid=threadIdx.x, warp=tid>>5, lane=tid&31;
    const int wm=(warp&1)*64, wn=(warp>>1)*32;
    const int ar=lane>>2, ac=lane&3;
    const int nk=(m0+128)>>5;

    float acc[4][4][4];
    #pragma unroll
    for (int i=0;i<4;i++)
        #pragma unroll
        for (int j=0;j<4;j++)
            #pragma unroll
            for (int r=0;r<4;r++) acc[i][j][r]=0.f;

    const int vd  = tid & 127;          // d index base (plus p*... below uses f)
    uint2 ra[4], rb[4];

    // prologue: V(0) + A(0)
    #pragma unroll
    for (int p=0;p<4;p++){
        int f=p*256+tid; int d=f&127; int kb=(f>>7)*4;
        float f0=vb[(long long)(kb+0)*DD+d], f1=vb[(long long)(kb+1)*DD+d];
        float f2=vb[(long long)(kb+2)*DD+d], f3=vb[(long long)(kb+3)*DD+d];
        ra[p].x=pbf2(f0,f1); ra[p].y=pbf2(f2,f3);
    }
    #pragma unroll
    for (int p=0;p<2;p++){
        int f=p*256+tid; int row=f>>2, c8=(f&3)*8;
        cpa16(&AS[0][row*40+c8], Pb + (long long)(m0+row)*LL + c8);
    }
    cp_commit();
    #pragma unroll
    for (int p=0;p<4;p++){
        int f=p*256+tid; int d=f&127; int kb=(f>>7)*4;
        *(uint2*)&VS[0][d*40+kb] = ra[p];
    }
    cp_wait<0>();
    __syncthreads();

    for (int i=0;i<nk;i++){
        if (i+1<nk){
            int k0=(i+1)<<5;
            #pragma unroll
            for (int p=0;p<4;p++){
                int f=p*256+tid; int d=f&127; int kb=(f>>7)*4;
                float f0=vb[(long long)(k0+kb+0)*DD+d], f1=vb[(long long)(k0+kb+1)*DD+d];
                float f2=vb[(long long)(k0+kb+2)*DD+d], f3=vb[(long long)(k0+kb+3)*DD+d];
                rb[p].x=pbf2(f0,f1); rb[p].y=pbf2(f2,f3);
            }
            #pragma unroll
            for (int p=0;p<2;p++){
                int f=p*256+tid; int row=f>>2, c8=(f&3)*8;
                cpa16(&AS[(i+1)&1][row*40+c8], Pb + (long long)(m0+row)*LL + k0 + c8);
            }
            cp_commit();
        }
        const int bc=i&1;
        #pragma unroll
        for (int ks=0;ks<2;ks++){
            const int kc=ks*16;
            unsigned af[4][4];
            #pragma unroll
            for (int mi=0;mi<4;mi++){
                int r0=wm+mi*16+ar;
                af[mi][0]=*(const unsigned*)&AS[bc][(r0  )*40+kc+ac*2  ];
                af[mi][1]=*(const unsigned*)&AS[bc][(r0+8)*40+kc+ac*2  ];
                af[mi][2]=*(const unsigned*)&AS[bc][(r0  )*40+kc+8+ac*2];
                af[mi][3]=*(const unsigned*)&AS[bc][(r0+8)*40+kc+8+ac*2];
            }
            #pragma unroll
            for (int ni=0;ni<4;ni++){
                int n=wn+ni*8+ar;
                unsigned bf[2];
                bf[0]=*(const unsigned*)&VS[bc][n*40+kc+ac*2  ];
                bf[1]=*(const unsigned*)&VS[bc][n*40+kc+8+ac*2];
                #pragma unroll
                for (int mi=0;mi<4;mi++) mma_bf16(acc[mi][ni], af[mi], bf);
            }
        }
        __syncthreads();
        if (i+1<nk){
            #pragma unroll
            for (int p=0;p<4;p++){
                int f=p*256+tid; int d=f&127; int kb=(f>>7)*4;
                *(uint2*)&VS[(i+1)&1][d*40+kb] = rb[p];
            }
            cp_wait<0>();
            __syncthreads();
        }
    }

    const int er=lane>>2, ec=(lane&3)*2;
    #pragma unroll
    for (int mi=0;mi<4;mi++){
        #pragma unroll
        for (int half=0; half<2; half++){
            long long gm = m0 + wm + mi*16 + er + half*8;
            float* crow = mb + gm*(long long)DD;
            #pragma unroll
            for (int ni=0;ni<4;ni++){
                int gn = wn + ni*8 + ec;
                float2 o; o.x=acc[mi][ni][half*2+0]; o.y=acc[mi][ni][half*2+1];
                *(float2*)(crow + gn) = o;
            }
        }
    }
}

// ---------------- host orchestration ----------------
extern "C" void kernel_launch(void* const* d_in, const int* in_sizes, int n_in,
                              void* d_out, int out_size){
    (void)in_sizes; (void)n_in; (void)out_size;
    const float* item   = (const float*)d_in[0];
    const float* posemb = (const float*)d_in[1];
    const float* pre_w  = (const float*)d_in[2];
    const float* pre_b  = (const float*)d_in[3];
    const float* ln1_s  = (const float*)d_in[4];
    const float* ln1_b  = (const float*)d_in[5];
    const float* in_w   = (const float*)d_in[6];
    const float* in_b   = (const float*)d_in[7];
    const float* out_w  = (const float*)d_in[8];
    const float* out_b  = (const float*)d_in[9];
    const float* ln2_s  = (const float*)d_in[10];
    const float* ln2_b  = (const float*)d_in[11];
    const float* c1_w   = (const float*)d_in[12];
    const float* c1_b   = (const float*)d_in[13];
    const float* c2_w   = (const float*)d_in[14];
    const float* c2_b   = (const float*)d_in[15];
    const float* lnf_s  = (const float*)d_in[16];
    const float* lnf_b  = (const float*)d_in[17];
    const int* logs = (const int*)d_in[19];
    const int* poss = (const int*)d_in[20];
    const int* negs = (const int*)d_in[21];
    float* out = (float*)d_out;

    float *seqs,*Q,*q,*k,*v,*qp,*mha,*tmp,*attn,*E,*cape;
    __nv_bfloat16* attnh;
    cudaGetSymbolAddress((void**)&seqs, g_seqs);
    cudaGetSymbolAddress((void**)&Q,    g_Q);
    cudaGetSymbolAddress((void**)&q,    g_q);
    cudaGetSymbolAddress((void**)&k,    g_k);
    cudaGetSymbolAddress((void**)&v,    g_v);
    cudaGetSymbolAddress((void**)&qp,   g_qp);
    cudaGetSymbolAddress((void**)&mha,  g_mha);
    cudaGetSymbolAddress((void**)&tmp,  g_tmp);
    cudaGetSymbolAddress((void**)&attn, g_attn);
    cudaGetSymbolAddress((void**)&attnh,g_attnh);
    cudaGetSymbolAddress((void**)&E,    g_E);
    cudaGetSymbolAddress((void**)&cape, g_cape);

    const int ROWB = BL/8;
    const float scale = 0.08838834764831845f; // 1/sqrt(128)
    const int GPSM = 2*4608*4*2;    // 73,728 B dynamic smem for gemm_p
    const int ESM  = 2*128*136*2;   // 69,632 B dynamic smem for gemm_e

    static int once = 0;
    if (!once){
        cudaFuncSetAttribute(gemm_p<0,2,true,false>,  cudaFuncAttributeMaxDynamicSharedMemorySize, GPSM);
        cudaFuncSetAttribute(gemm_p<0,0,true,false>,  cudaFuncAttributeMaxDynamicSharedMemorySize, GPSM);
        cudaFuncSetAttribute(gemm_p<0,0,false,true>,  cudaFuncAttributeMaxDynamicSharedMemorySize, GPSM);
        cudaFuncSetAttribute(gemm_p<0,0,false,false>, cudaFuncAttributeMaxDynamicSharedMemorySize, GPSM);
        cudaFuncSetAttribute(gemm_p<1,0,false,false>, cudaFuncAttributeMaxDynamicSharedMemorySize, GPSM);
        cudaFuncSetAttribute(gemm_e, cudaFuncAttributeMaxDynamicSharedMemorySize, ESM);
        once = 1;
    }

    embed_k<<<ROWB,256>>>(item, logs, seqs);

    for (int i=0;i<2;i++){
        const float* wq = in_w + (long long)i*3*DD*DD;
        const float* wk = wq + DD*DD;
        const float* wv = wk + DD*DD;
        const float* bq = in_b + (long long)i*3*DD;
        const float* bk = bq + DD;
        const float* bv = bk + DD;

        ln_k<false><<<ROWB,256>>>(seqs, nullptr, ln1_s+i*DD, ln1_b+i*DD, Q);

        // dual GEMMs: (q, qp) from Q;  (k, v) from seqs
        dim3 gd(2, BL/128);
        gemm_p<0,2,true,false><<<gd,256,GPSM>>>(Q, wq, bq, nullptr, q,
                                                pre_w, pre_b, qp,
                                                BL, DD, DD, 0,0,0, 1.f);
        gemm_p<0,0,true,false><<<gd,256,GPSM>>>(seqs, wk, bk, nullptr, k,
                                                wv, bv, v,
                                                BL, DD, DD, 0,0,0, 1.f);

        // E = qp @ pos_emb  (bf16 tensor cores, single-shot K=128)
        gemm_e<<<dim3(4, BL/128),256,ESM>>>(qp, posemb, E);

        // scores = q.k^T * scale  (skip fully-masked upper tiles)
        dim3 gsc(4,4,BB);
        gemm_p<0,0,false,true><<<gsc,256,GPSM>>>(q, k, nullptr, nullptr, attn,
            nullptr,nullptr,nullptr,
            LL, LL, DD, (long long)LL*DD, (long long)LL*DD, (long long)LL*LL, scale);

        // fused softmax + CAPE (reads fp32 scores, writes bf16 probs + cape)
        softcape_k<<<ROWB,256>>>(attn, attnh, E, cape);

        // mha = probs(bf16) @ v   (causal K-limit per m-tile)
        av_bf16<<<dim3(4,BB),256>>>(attnh, v, mha);

        // seqs = Q + mha.out_w^T + out_b
        dim3 gl(1, BL/128);
        gemm_p<0,0,false,false><<<gl,256,GPSM>>>(mha, out_w+(long long)i*DD*DD,
                                                 out_b+i*DD, Q, seqs,
                                                 nullptr,nullptr,nullptr,
                                                 BL, DD, DD, 0,0,0, 1.f);

        // seqs = LN2(seqs + cape)  -> X (stored in Q buffer)
        ln_k<true><<<ROWB,256>>>(seqs, cape, ln2_s+i*DD, ln2_b+i*DD, Q);

        // FFN
        gemm_p<1,0,false,false><<<gl,256,GPSM>>>(Q, c1_w+(long long)i*DD*DD,
                                                 c1_b+i*DD, nullptr, tmp,
                                                 nullptr,nullptr,nullptr,
                                                 BL, DD, DD, 0,0,0, 1.f);
        gemm_p<0,0,false,false><<<gl,256,GPSM>>>(tmp, c2_w+(long long)i*DD*DD,
                                                 c2_b+i*DD, Q, seqs,
                                                 nullptr,nullptr,nullptr,
                                                 BL, DD, DD, 0,0,0, 1.f);
    }

    final_k<<<ROWB,256>>>(seqs, item, lnf_s, lnf_b, poss, negs, out);
}

// round 12
// speedup vs baseline: 1.2005x; 1.0451x over previous
#include <cuda_runtime.h>
#include <cuda_bf16.h>
#include <math.h>

#define BB 128
#define LL 512
#define DD 128
#define BL (BB*LL)
#define ML 512

// ---------------- scratch (static device globals; no allocations) ----------------
__device__ float g_seqs[BL*DD];
__device__ float g_Q   [BL*DD];
__device__ float g_q   [BL*DD];
__device__ float g_k   [BL*DD];
__device__ float g_v   [BL*DD];
__device__ float g_qp  [BL*DD];
__device__ float g_mha [BL*DD];
__device__ float g_tmp [BL*DD];
__device__ float g_attn[BB*LL*LL];            // fp32 raw scores
__device__ __nv_bfloat16 g_attnh[BB*LL*LL];   // bf16 normalized probs
__device__ float g_E   [BL*ML];
__device__ float g_cape[BL];

// ---------------- helpers ----------------
__device__ __forceinline__ float wredsum(float v){
    #pragma unroll
    for (int o=16;o>0;o>>=1) v += __shfl_xor_sync(0xffffffffu, v, o);
    return v;
}
__device__ __forceinline__ float wredmax(float v){
    #pragma unroll
    for (int o=16;o>0;o>>=1) v = fmaxf(v, __shfl_xor_sync(0xffffffffu, v, o));
    return v;
}
__device__ __forceinline__ void mma_tf32(float* d, const unsigned* a, const unsigned* b){
    asm volatile(
        "mma.sync.aligned.m16n8k8.row.col.f32.tf32.tf32.f32 "
        "{%0,%1,%2,%3},{%4,%5,%6,%7},{%8,%9},{%0,%1,%2,%3};"
        : "+f"(d[0]),"+f"(d[1]),"+f"(d[2]),"+f"(d[3])
        : "r"(a[0]),"r"(a[1]),"r"(a[2]),"r"(a[3]), "r"(b[0]),"r"(b[1]));
}
__device__ __forceinline__ void mma_bf16(float* d, const unsigned* a, const unsigned* b){
    asm volatile(
        "mma.sync.aligned.m16n8k16.row.col.f32.bf16.bf16.f32 "
        "{%0,%1,%2,%3},{%4,%5,%6,%7},{%8,%9},{%0,%1,%2,%3};"
        : "+f"(d[0]),"+f"(d[1]),"+f"(d[2]),"+f"(d[3])
        : "r"(a[0]),"r"(a[1]),"r"(a[2]),"r"(a[3]), "r"(b[0]),"r"(b[1]));
}
__device__ __forceinline__ void cpa16(void* s, const void* g){
    unsigned sa = (unsigned)__cvta_generic_to_shared(s);
    asm volatile("cp.async.cg.shared.global [%0],[%1],16;\n" :: "r"(sa),"l"(g));
}
__device__ __forceinline__ void cp_commit(){ asm volatile("cp.async.commit_group;\n"); }
template<int N> __device__ __forceinline__ void cp_wait(){ asm volatile("cp.async.wait_group %0;\n"::"n"(N)); }
__device__ __forceinline__ unsigned fu(float f){ return __float_as_uint(f); }
__device__ __forceinline__ unsigned pbf2(float a, float b){
    __nv_bfloat162 h = __floats2bfloat162_rn(a,b);
    return *(unsigned*)&h;
}

// ---------------- embedding gather + fused LN1 ----------------
// seqs = item_emb[log_seqs]*sqrt(D); Q = LN1(seqs)
__global__ void embed_ln_k(const float* __restrict__ item, const int* __restrict__ idx,
                           const float* __restrict__ gs, const float* __restrict__ gb,
                           float* __restrict__ seqs, float* __restrict__ Qo){
    int row  = blockIdx.x*8 + (threadIdx.x>>5);
    int lane = threadIdx.x & 31;
    int id = idx[row];
    float4 v = *(const float4*)(item + (long long)id*DD + lane*4);
    const float s = 11.313708498984760f; // sqrt(128)
    v.x*=s; v.y*=s; v.z*=s; v.w*=s;
    *(float4*)(seqs + (long long)row*DD + lane*4) = v;
    float m = wredsum(v.x+v.y+v.z+v.w) * (1.0f/DD);
    float dx=v.x-m, dy=v.y-m, dz=v.z-m, dw=v.w-m;
    float var = wredsum(dx*dx+dy*dy+dz*dz+dw*dw) * (1.0f/DD);
    float r = rsqrtf(var + 1e-8f);
    float4 o;
    o.x = dx*r*gs[lane*4+0] + gb[lane*4+0];
    o.y = dy*r*gs[lane*4+1] + gb[lane*4+1];
    o.z = dz*r*gs[lane*4+2] + gb[lane*4+2];
    o.w = dw*r*gs[lane*4+3] + gb[lane*4+3];
    *(float4*)(Qo + (long long)row*DD + lane*4) = o;
}

// ---------------- fused causal softmax + CAPE ----------------
__global__ void softcape_k(const float* __restrict__ attn, __nv_bfloat16* __restrict__ ph,
                           const float* __restrict__ E, float* __restrict__ cape){
    __shared__ float es[8][ML];
    __shared__ float gsm[8][32][17];
    int w    = threadIdx.x>>5;
    int lane = threadIdx.x & 31;
    int row  = blockIdx.x*8 + w;
    int qi = row & (LL-1);
    const float* p = attn + (long long)row*LL;
    __nv_bfloat16* po = ph + (long long)row*LL;
    const float* er = E + (long long)row*ML;
    #pragma unroll
    for (int t=0;t<16;t++) es[w][t*32+lane] = er[t*32+lane];

    int nv = qi+1;
    float vals[16];
    float mx = -3.4e38f;
    #pragma unroll
    for (int t=0;t<16;t++){
        int j = t*32+lane;
        float s = (j<nv) ? p[j] : -3.4e38f;
        vals[t]=s; mx = fmaxf(mx, s);
    }
    mx = wredmax(mx);
    float sum = 0.f;
    #pragma unroll
    for (int t=0;t<16;t++){
        int j = t*32+lane;
        float e = (j<nv) ? __expf(vals[t]-mx) : 0.f;
        vals[t]=e; sum += e;
    }
    sum = wredsum(sum);
    float inv = 1.0f/sum;
    #pragma unroll
    for (int t=0;t<16;t++){
        int j = t*32+lane;
        float pv = vals[t]*inv;
        po[j] = __float2bfloat16(pv);
        float g = 1.0f/(1.0f+__expf(pv));   // 1 - sigmoid(pv); masked pv=0 -> 0.5 (matches ref)
        gsm[w][j>>4][j&15] = g;
    }
    __syncwarp();
    float cs = 0.f;
    #pragma unroll
    for (int t=0;t<16;t++) cs += gsm[w][lane][t];
    float sfx = cs;
    #pragma unroll
    for (int off=1;off<32;off<<=1){
        float o = __shfl_down_sync(0xffffffffu, sfx, off);
        if (lane+off < 32) sfx += o;
    }
    float tail = sfx - cs;
    float run = 0.f, acc = 0.f;
    #pragma unroll
    for (int t=15;t>=0;t--){
        run += gsm[w][lane][t];
        float P = run + tail;
        P = fminf(P, (float)(ML-1));
        float Pf = floorf(P);
        float fr = P - Pf;
        int pi = (int)Pf;
        int pc = (int)ceilf(P);
        float ef = es[w][pi];
        float ec = es[w][pc];
        acc += fr*ec + (1.0f-fr)*ef;
    }
    acc = wredsum(acc);
    if (lane==0) cape[row] = acc * (1.0f/LL);
}

// ---------------- final: dot of pre-LN'd feats with pos/neg item embeddings ----------------
__global__ void final_k(const float* __restrict__ feats, const float* __restrict__ item,
                        const int* __restrict__ pos, const int* __restrict__ neg,
                        float* __restrict__ out){
    int row  = blockIdx.x*8 + (threadIdx.x>>5);
    int lane = threadIdx.x & 31;
    float4 f = *(const float4*)(feats + (long long)row*DD + lane*4);
    int pi = pos[row], ni = neg[row];
    float4 pe = *(const float4*)(item + (long long)pi*DD + lane*4);
    float4 ne = *(const float4*)(item + (long long)ni*DD + lane*4);
    float dp = f.x*pe.x + f.y*pe.y + f.z*pe.z + f.w*pe.w;
    float dn = f.x*ne.x + f.y*ne.y + f.z*ne.z + f.w*ne.w;
    dp = wredsum(dp); dn = wredsum(dn);
    if (lane==0){ out[row] = dp; out[BL+row] = dn; }
}

// ---------------- pipelined TF32 GEMM, k32 steps, dynamic smem ----------------
// Base: C = act(alpha*A.B^T + bias) + res.  A [M,K], B [N,K] row-major.  K%32==0.
// 128x128 block tile, 256 thr, warp tile 64x32, 2-stage cp.async.
// DUAL: grid.x==2 selects (Bm,bias,C,ACT) / (Bm2,bias2,C2,ACT2); n0=0.
// SKIPUP: skip tiles fully above causal diagonal (scores).
// EPILN: epilogue computes y = alpha*A.B^T + bias + res + cape[row], then
//        Cln = LN(y; lns,lnb) (full row per CTA; requires N==128, grid.x==1).
//        WRAW additionally writes raw y to C.
template<int ACT, int ACT2, bool DUAL, bool SKIPUP, bool EPILN, bool WRAW>
__global__ __launch_bounds__(256,2)
void gemm_p(const float* __restrict__ A, const float* __restrict__ Bm,
            const float* __restrict__ bias, const float* __restrict__ res,
            float* __restrict__ C,
            const float* __restrict__ Bm2, const float* __restrict__ bias2,
            float* __restrict__ C2,
            const float* __restrict__ lns, const float* __restrict__ lnb,
            const float* __restrict__ capev, float* __restrict__ Cln,
            int M, int N, int K,
            long long sA, long long sB, long long sC, float alpha)
{
    if (SKIPUP && (int)blockIdx.x > (int)blockIdx.y) return;
    const int bz = blockIdx.z;
    A += (long long)bz*sA;
    int actv = ACT;
    if (DUAL){
        if (blockIdx.x == 1){ Bm = Bm2; bias = bias2; C = C2; actv = ACT2; }
    } else {
        Bm += (long long)bz*sB;
        C  += (long long)bz*sC;
        if (res) res += (long long)bz*sC;
    }

    extern __shared__ float sm_g[];
    float* As = sm_g;            // 2 x [128][36]
    float* Bs = sm_g + 2*4608;   // 2 x [128][36]

    const int tid=threadIdx.x, warp=tid>>5, lane=tid&31;
    const int wm=(warp&1)*64, wn=(warp>>1)*32;
    const int m0=blockIdx.y*128;
    const int n0=DUAL ? 0 : blockIdx.x*128;
    const int ar=lane>>2, ac=lane&3;
    const int nk = K>>5;
    const int lrow = tid>>3, lc4 = (tid&7)*4;

    float acc[4][4][4];
    #pragma unroll
    for (int i=0;i<4;i++)
        #pragma unroll
        for (int j=0;j<4;j++)
            #pragma unroll
            for (int r=0;r<4;r++) acc[i][j][r]=0.f;

    // stage 0
    {
        float* as = As; float* bs = Bs;
        #pragma unroll
        for (int p=0;p<4;p++){
            int row = p*32 + lrow;
            cpa16(&as[row*36+lc4], A  + (long long)(m0+row)*K + lc4);
            cpa16(&bs[row*36+lc4], Bm + (long long)(n0+row)*K + lc4);
        }
        cp_commit();
    }

    for (int i=0;i<nk;i++){
        if (i+1<nk){
            int bn=(i+1)&1, k0=(i+1)<<5;
            float* as = As + bn*4608; float* bs = Bs + bn*4608;
            #pragma unroll
            for (int p=0;p<4;p++){
                int row = p*32 + lrow;
                cpa16(&as[row*36+lc4], A  + (long long)(m0+row)*K + k0 + lc4);
                cpa16(&bs[row*36+lc4], Bm + (long long)(n0+row)*K + k0 + lc4);
            }
            cp_commit();
            cp_wait<1>();
        } else {
            cp_wait<0>();
        }
        __syncthreads();
        const float* as = As + (i&1)*4608;
        const float* bs = Bs + (i&1)*4608;
        #pragma unroll
        for (int s8=0;s8<4;s8++){
            const int kb=s8*8;
            unsigned af[4][4];
            #pragma unroll
            for (int mi=0;mi<4;mi++){
                int r0=wm+mi*16+ar;
                af[mi][0]=fu(as[(r0  )*36+kb+ac  ]);
                af[mi][1]=fu(as[(r0+8)*36+kb+ac  ]);
                af[mi][2]=fu(as[(r0  )*36+kb+ac+4]);
                af[mi][3]=fu(as[(r0+8)*36+kb+ac+4]);
            }
            #pragma unroll
            for (int ni=0;ni<4;ni++){
                int nr=wn+ni*8+ar;
                unsigned bf[2];
                bf[0]=fu(bs[nr*36+kb+ac  ]);
                bf[1]=fu(bs[nr*36+kb+ac+4]);
                #pragma unroll
                for (int mi=0;mi<4;mi++) mma_tf32(acc[mi][ni], af[mi], bf);
            }
        }
        __syncthreads();
    }

    const int er=lane>>2, ec=(lane&3)*2;
    if (!EPILN){
        #pragma unroll
        for (int mi=0;mi<4;mi++){
            #pragma unroll
            for (int half=0; half<2; half++){
                long long gm = m0 + wm + mi*16 + er + half*8;
                float* crow = C + gm*(long long)N;
                const float* rrow = res ? (res + gm*(long long)N) : nullptr;
                #pragma unroll
                for (int ni=0;ni<4;ni++){
                    int gn = n0 + wn + ni*8 + ec;
                    float v0 = acc[mi][ni][half*2+0]*alpha;
                    float v1 = acc[mi][ni][half*2+1]*alpha;
                    if (bias){ v0 += bias[gn]; v1 += bias[gn+1]; }
                    if (actv==1){ v0 = fmaxf(v0,0.f); v1 = fmaxf(v1,0.f); }
                    if (actv==2){ v0 = v0/(1.0f+__expf(-v0)); v1 = v1/(1.0f+__expf(-v1)); }
                    if (rrow){ v0 += rrow[gn]; v1 += rrow[gn+1]; }
                    float2 o; o.x=v0; o.y=v1;
                    *(float2*)(crow + gn) = o;
                }
            }
        }
    } else {
        // fused LayerNorm epilogue (N==128, full row per CTA)
        __shared__ float2 red[128][4];
        const int wnidx = warp>>1;
        #pragma unroll
        for (int mi=0;mi<4;mi++){
            #pragma unroll
            for (int half=0; half<2; half++){
                int r = wm + mi*16 + er + half*8;
                long long gm = m0 + r;
                const float* rrow = res ? (res + gm*(long long)N) : nullptr;
                float cv = capev ? capev[gm] : 0.f;
                float s1=0.f, s2=0.f;
                #pragma unroll
                for (int ni=0;ni<4;ni++){
                    #pragma unroll
                    for (int u=0;u<2;u++){
                        int gn = wn + ni*8 + ec + u;
                        float v0 = acc[mi][ni][half*2+u]*alpha;
                        if (bias) v0 += bias[gn];
                        if (rrow) v0 += rrow[gn];
                        v0 += cv;
                        acc[mi][ni][half*2+u] = v0;
                        s1 += v0; s2 += v0*v0;
                    }
                }
                s1 += __shfl_xor_sync(0xffffffffu, s1, 1);
                s2 += __shfl_xor_sync(0xffffffffu, s2, 1);
                s1 += __shfl_xor_sync(0xffffffffu, s1, 2);
                s2 += __shfl_xor_sync(0xffffffffu, s2, 2);
                if ((lane&3)==0) red[r][wnidx] = make_float2(s1, s2);
            }
        }
        __syncthreads();
        #pragma unroll
        for (int mi=0;mi<4;mi++){
            #pragma unroll
            for (int half=0; half<2; half++){
                int r = wm + mi*16 + er + half*8;
                long long gm = m0 + r;
                float2 p0=red[r][0], p1=red[r][1], p2=red[r][2], p3=red[r][3];
                float S1 = p0.x+p1.x+p2.x+p3.x;
                float S2 = p0.y+p1.y+p2.y+p3.y;
                float mean = S1*(1.0f/DD);
                float var  = S2*(1.0f/DD) - mean*mean;
                float rr   = rsqrtf(var + 1e-8f);
                float* lrow = Cln + gm*(long long)N;
                float* crow = WRAW ? (C + gm*(long long)N) : nullptr;
                #pragma unroll
                for (int ni=0;ni<4;ni++){
                    int gn = wn + ni*8 + ec;
                    float v0 = acc[mi][ni][half*2+0];
                    float v1 = acc[mi][ni][half*2+1];
                    float o0 = (v0-mean)*rr*lns[gn  ] + lnb[gn  ];
                    float o1 = (v1-mean)*rr*lns[gn+1] + lnb[gn+1];
                    *(float2*)(lrow + gn) = make_float2(o0, o1);
                    if (WRAW) *(float2*)(crow + gn) = make_float2(v0, v1);
                }
            }
        }
    }
}

// ---------------- bf16 single-shot GEMM for E = qp @ pos_emb ----------------
__global__ __launch_bounds__(256,2)
void gemm_e(const float* __restrict__ qp, const float* __restrict__ pe,
            float* __restrict__ E)
{
    extern __shared__ __nv_bfloat16 sm_e[];
    __nv_bfloat16* AS = sm_e;            // [128 m][136 k]
    __nv_bfloat16* BS = sm_e + 128*136;  // [128 n][136 k]

    const int tid=threadIdx.x, warp=tid>>5, lane=tid&31;
    const int n0=blockIdx.x*128;
    const long long m0=(long long)blockIdx.y*128;
    const int wm=(warp&1)*64, wn=(warp>>1)*32;
    const int ar=lane>>2, ac=lane&3;

    #pragma unroll
    for (int p=0;p<16;p++){
        int f=p*256+tid;
        int m=f>>5, k4=(f&31)*4;
        float4 a = *(const float4*)(qp + (m0+m)*DD + k4);
        uint2 u; u.x=pbf2(a.x,a.y); u.y=pbf2(a.z,a.w);
        *(uint2*)&AS[m*136+k4] = u;
    }
    #pragma unroll
    for (int p=0;p<16;p++){
        int f=p*256+tid;
        int n=f&127, kb=(f>>7)*4;
        float b0=pe[(kb+0)*ML+n0+n], b1=pe[(kb+1)*ML+n0+n];
        float b2=pe[(kb+2)*ML+n0+n], b3=pe[(kb+3)*ML+n0+n];
        uint2 u; u.x=pbf2(b0,b1); u.y=pbf2(b2,b3);
        *(uint2*)&BS[n*136+kb] = u;
    }
    __syncthreads();

    float acc[4][4][4];
    #pragma unroll
    for (int i=0;i<4;i++)
        #pragma unroll
        for (int j=0;j<4;j++)
            #pragma unroll
            for (int r=0;r<4;r++) acc[i][j][r]=0.f;

    #pragma unroll
    for (int ks=0;ks<8;ks++){
        const int kc=ks*16;
        unsigned af[4][4];
        #pragma unroll
        for (int mi=0;mi<4;mi++){
            int r0=wm+mi*16+ar;
            af[mi][0]=*(const unsigned*)&AS[(r0  )*136+kc+ac*2  ];
            af[mi][1]=*(const unsigned*)&AS[(r0+8)*136+kc+ac*2  ];
            af[mi][2]=*(const unsigned*)&AS[(r0  )*136+kc+8+ac*2];
            af[mi][3]=*(const unsigned*)&AS[(r0+8)*136+kc+8+ac*2];
        }
        #pragma unroll
        for (int ni=0;ni<4;ni++){
            int n=wn+ni*8+ar;
            unsigned bf[2];
            bf[0]=*(const unsigned*)&BS[n*136+kc+ac*2  ];
            bf[1]=*(const unsigned*)&BS[n*136+kc+8+ac*2];
            #pragma unroll
            for (int mi=0;mi<4;mi++) mma_bf16(acc[mi][ni], af[mi], bf);
        }
    }

    const int er=lane>>2, ec=(lane&3)*2;
    #pragma unroll
    for (int mi=0;mi<4;mi++){
        #pragma unroll
        for (int half=0; half<2; half++){
            long long gm = m0 + wm + mi*16 + er + half*8;
            float* crow = E + gm*(long long)ML;
            #pragma unroll
            for (int ni=0;ni<4;ni++){
                int gn = n0 + wn + ni*8 + ec;
                float2 o; o.x=acc[mi][ni][half*2+0]; o.y=acc[mi][ni][half*2+1];
                *(float2*)(crow + gn) = o;
            }
        }
    }
}

// ---------------- bf16 AV GEMM: mha = probs(bf16) @ v, double-buffered ----------------
__global__ __launch_bounds__(256,2)
void av_bf16(const __nv_bfloat16* __restrict__ P, const float* __restrict__ v,
             float* __restrict__ mha)
{
    const int b=blockIdx.y, m0=blockIdx.x*128;
    const __nv_bfloat16* Pb = P + (long long)b*LL*LL;
    const float* vb = v + (long long)b*LL*DD;
    float* mb = mha + (long long)b*LL*DD;

    __shared__ __align__(16) __nv_bfloat16 AS[2][128*40];
    __shared__ __align__(16) __nv_bfloat16 VS[2][128*40];

    const int tid=threadIdx.x, warp=tid>>5, lane=tid&31;
    const int wm=(warp&1)*64, wn=(warp>>1)*32;
    const int ar=lane>>2, ac=lane&3;
    const int nk=(m0+128)>>5;

    float acc[4][4][4];
    #pragma unroll
    for (int i=0;i<4;i++)
        #pragma unroll
        for (int j=0;j<4;j++)
            #pragma unroll
            for (int r=0;r<4;r++) acc[i][j][r]=0.f;

    uint2 ra[4], rb[4];

    #pragma unroll
    for (int p=0;p<4;p++){
        int f=p*256+tid; int d=f&127; int kb=(f>>7)*4;
        float f0=vb[(long long)(kb+0)*DD+d], f1=vb[(long long)(kb+1)*DD+d];
        float f2=vb[(long long)(kb+2)*DD+d], f3=vb[(long long)(kb+3)*DD+d];
        ra[p].x=pbf2(f0,f1); ra[p].y=pbf2(f2,f3);
    }
    #pragma unroll
    for (int p=0;p<2;p++){
        int f=p*256+tid; int row=f>>2, c8=(f&3)*8;
        cpa16(&AS[0][row*40+c8], Pb + (long long)(m0+row)*LL + c8);
    }
    cp_commit();
    #pragma unroll
    for (int p=0;p<4;p++){
        int f=p*256+tid; int d=f&127; int kb=(f>>7)*4;
        *(uint2*)&VS[0][d*40+kb] = ra[p];
    }
    cp_wait<0>();
    __syncthreads();

    for (int i=0;i<nk;i++){
        if (i+1<nk){
            int k0=(i+1)<<5;
            #pragma unroll
            for (int p=0;p<4;p++){
                int f=p*256+tid; int d=f&127; int kb=(f>>7)*4;
                float f0=vb[(long long)(k0+kb+0)*DD+d], f1=vb[(long long)(k0+kb+1)*DD+d];
                float f2=vb[(long long)(k0+kb+2)*DD+d], f3=vb[(long long)(k0+kb+3)*DD+d];
                rb[p].x=pbf2(f0,f1); rb[p].y=pbf2(f2,f3);
            }
            #pragma unroll
            for (int p=0;p<2;p++){
                int f=p*256+tid; int row=f>>2, c8=(f&3)*8;
                cpa16(&AS[(i+1)&1][row*40+c8], Pb + (long long)(m0+row)*LL + k0 + c8);
            }
            cp_commit();
        }
        const int bc=i&1;
        #pragma unroll
        for (int ks=0;ks<2;ks++){
            const int kc=ks*16;
            unsigned af[4][4];
            #pragma unroll
            for (int mi=0;mi<4;mi++){
                int r0=wm+mi*16+ar;
                af[mi][0]=*(const unsigned*)&AS[bc][(r0  )*40+kc+ac*2  ];
                af[mi][1]=*(const unsigned*)&AS[bc][(r0+8)*40+kc+ac*2  ];
                af[mi][2]=*(const unsigned*)&AS[bc][(r0  )*40+kc+8+ac*2];
                af[mi][3]=*(const unsigned*)&AS[bc][(r0+8)*40+kc+8+ac*2];
            }
            #pragma unroll
            for (int ni=0;ni<4;ni++){
                int n=wn+ni*8+ar;
                unsigned bf[2];
                bf[0]=*(const unsigned*)&VS[bc][n*40+kc+ac*2  ];
                bf[1]=*(const unsigned*)&VS[bc][n*40+kc+8+ac*2];
                #pragma unroll
                for (int mi=0;mi<4;mi++) mma_bf16(acc[mi][ni], af[mi], bf);
            }
        }
        __syncthreads();
        if (i+1<nk){
            #pragma unroll
            for (int p=0;p<4;p++){
                int f=p*256+tid; int d=f&127; int kb=(f>>7)*4;
                *(uint2*)&VS[(i+1)&1][d*40+kb] = rb[p];
            }
            cp_wait<0>();
            __syncthreads();
        }
    }

    const int er=lane>>2, ec=(lane&3)*2;
    #pragma unroll
    for (int mi=0;mi<4;mi++){
        #pragma unroll
        for (int half=0; half<2; half++){
            long long gm = m0 + wm + mi*16 + er + half*8;
            float* crow = mb + gm*(long long)DD;
            #pragma unroll
            for (int ni=0;ni<4;ni++){
                int gn = wn + ni*8 + ec;
                float2 o; o.x=acc[mi][ni][half*2+0]; o.y=acc[mi][ni][half*2+1];
                *(float2*)(crow + gn) = o;
            }
        }
    }
}

// ---------------- host orchestration ----------------
extern "C" void kernel_launch(void* const* d_in, const int* in_sizes, int n_in,
                              void* d_out, int out_size){
    (void)in_sizes; (void)n_in; (void)out_size;
    const float* item   = (const float*)d_in[0];
    const float* posemb = (const float*)d_in[1];
    const float* pre_w  = (const float*)d_in[2];
    const float* pre_b  = (const float*)d_in[3];
    const float* ln1_s  = (const float*)d_in[4];
    const float* ln1_b  = (const float*)d_in[5];
    const float* in_w   = (const float*)d_in[6];
    const float* in_b   = (const float*)d_in[7];
    const float* out_w  = (const float*)d_in[8];
    const float* out_b  = (const float*)d_in[9];
    const float* ln2_s  = (const float*)d_in[10];
    const float* ln2_b  = (const float*)d_in[11];
    const float* c1_w   = (const float*)d_in[12];
    const float* c1_b   = (const float*)d_in[13];
    const float* c2_w   = (const float*)d_in[14];
    const float* c2_b   = (const float*)d_in[15];
    const float* lnf_s  = (const float*)d_in[16];
    const float* lnf_b  = (const float*)d_in[17];
    const int* logs = (const int*)d_in[19];
    const int* poss = (const int*)d_in[20];
    const int* negs = (const int*)d_in[21];
    float* out = (float*)d_out;

    float *seqs,*Q,*q,*k,*v,*qp,*mha,*tmp,*attn,*E,*cape;
    __nv_bfloat16* attnh;
    cudaGetSymbolAddress((void**)&seqs, g_seqs);
    cudaGetSymbolAddress((void**)&Q,    g_Q);
    cudaGetSymbolAddress((void**)&q,    g_q);
    cudaGetSymbolAddress((void**)&k,    g_k);
    cudaGetSymbolAddress((void**)&v,    g_v);
    cudaGetSymbolAddress((void**)&qp,   g_qp);
    cudaGetSymbolAddress((void**)&mha,  g_mha);
    cudaGetSymbolAddress((void**)&tmp,  g_tmp);
    cudaGetSymbolAddress((void**)&attn, g_attn);
    cudaGetSymbolAddress((void**)&attnh,g_attnh);
    cudaGetSymbolAddress((void**)&E,    g_E);
    cudaGetSymbolAddress((void**)&cape, g_cape);

    const int ROWB = BL/8;
    const float scale = 0.08838834764831845f; // 1/sqrt(128)
    const int GPSM = 2*4608*4*2;    // 73,728 B dynamic smem for gemm_p
    const int ESM  = 2*128*136*2;   // 69,632 B dynamic smem for gemm_e

    static int once = 0;
    if (!once){
        cudaFuncSetAttribute(gemm_p<0,2,true,false,false,false>,  cudaFuncAttributeMaxDynamicSharedMemorySize, GPSM);
        cudaFuncSetAttribute(gemm_p<0,0,true,false,false,false>,  cudaFuncAttributeMaxDynamicSharedMemorySize, GPSM);
        cudaFuncSetAttribute(gemm_p<0,0,false,true,false,false>,  cudaFuncAttributeMaxDynamicSharedMemorySize, GPSM);
        cudaFuncSetAttribute(gemm_p<0,0,false,false,true,false>,  cudaFuncAttributeMaxDynamicSharedMemorySize, GPSM);
        cudaFuncSetAttribute(gemm_p<0,0,false,false,true,true>,   cudaFuncAttributeMaxDynamicSharedMemorySize, GPSM);
        cudaFuncSetAttribute(gemm_p<1,0,false,false,false,false>, cudaFuncAttributeMaxDynamicSharedMemorySize, GPSM);
        cudaFuncSetAttribute(gemm_e, cudaFuncAttributeMaxDynamicSharedMemorySize, ESM);
        once = 1;
    }

    // embed + fused LN1(block 0): writes seqs and Q
    embed_ln_k<<<ROWB,256>>>(item, logs, ln1_s, ln1_b, seqs, Q);

    for (int i=0;i<2;i++){
        const float* wq = in_w + (long long)i*3*DD*DD;
        const float* wk = wq + DD*DD;
        const float* wv = wk + DD*DD;
        const float* bq = in_b + (long long)i*3*DD;
        const float* bk = bq + DD;
        const float* bv = bk + DD;

        // dual GEMMs: (q, qp) from Q;  (k, v) from seqs
        dim3 gd(2, BL/128);
        gemm_p<0,2,true,false,false,false><<<gd,256,GPSM>>>(Q, wq, bq, nullptr, q,
                                                pre_w, pre_b, qp,
                                                nullptr,nullptr,nullptr,nullptr,
                                                BL, DD, DD, 0,0,0, 1.f);
        gemm_p<0,0,true,false,false,false><<<gd,256,GPSM>>>(seqs, wk, bk, nullptr, k,
                                                wv, bv, v,
                                                nullptr,nullptr,nullptr,nullptr,
                                                BL, DD, DD, 0,0,0, 1.f);

        // E = qp @ pos_emb  (bf16 tensor cores, single-shot K=128)
        gemm_e<<<dim3(4, BL/128),256,ESM>>>(qp, posemb, E);

        // scores = q.k^T * scale  (skip fully-masked upper tiles)
        dim3 gsc(4,4,BB);
        gemm_p<0,0,false,true,false,false><<<gsc,256,GPSM>>>(q, k, nullptr, nullptr, attn,
            nullptr,nullptr,nullptr,
            nullptr,nullptr,nullptr,nullptr,
            LL, LL, DD, (long long)LL*DD, (long long)LL*DD, (long long)LL*LL, scale);

        // fused softmax + CAPE (reads fp32 scores, writes bf16 probs + cape)
        softcape_k<<<ROWB,256>>>(attn, attnh, E, cape);

        // mha = probs(bf16) @ v   (causal K-limit per m-tile)
        av_bf16<<<dim3(4,BB),256>>>(attnh, v, mha);

        // X = LN2(Q + mha.out_w^T + out_b + cape)  -> written to Q buffer
        dim3 gl(1, BL/128);
        gemm_p<0,0,false,false,true,false><<<gl,256,GPSM>>>(mha, out_w+(long long)i*DD*DD,
                                                 out_b+i*DD, Q, seqs /*unused*/,
                                                 nullptr,nullptr,nullptr,
                                                 ln2_s+i*DD, ln2_b+i*DD, cape, Q,
                                                 BL, DD, DD, 0,0,0, 1.f);

        // FFN: h = relu(X.c1^T + b1)
        gemm_p<1,0,false,false,false,false><<<gl,256,GPSM>>>(Q, c1_w+(long long)i*DD*DD,
                                                 c1_b+i*DD, nullptr, tmp,
                                                 nullptr,nullptr,nullptr,
                                                 nullptr,nullptr,nullptr,nullptr,
                                                 BL, DD, DD, 0,0,0, 1.f);
        // seqs_raw = X + h.c2^T + b2 ; fused LN of NEXT stage:
        //   i==0: seqs written raw (for block-1 k/v), Q = LN1_b1(seqs_raw)
        //   i==1: feats = LNf(seqs_raw) -> g_v (raw not needed)
        if (i==0){
            gemm_p<0,0,false,false,true,true><<<gl,256,GPSM>>>(tmp, c2_w+(long long)i*DD*DD,
                                                 c2_b+i*DD, Q, seqs,
                                                 nullptr,nullptr,nullptr,
                                                 ln1_s+DD, ln1_b+DD, nullptr, Q,
                                                 BL, DD, DD, 0,0,0, 1.f);
        } else {
            gemm_p<0,0,false,false,true,false><<<gl,256,GPSM>>>(tmp, c2_w+(long long)i*DD*DD,
                                                 c2_b+i*DD, Q, seqs /*unused*/,
                                                 nullptr,nullptr,nullptr,
                                                 lnf_s, lnf_b, nullptr, v,
                                                 BL, DD, DD, 0,0,0, 1.f);
        }
    }

    // final: dot(feats, item_emb[pos/neg])
    final_k<<<ROWB,256>>>(v, item, poss, negs, out);
}